// round 2
// baseline (speedup 1.0000x reference)
#include <cuda_runtime.h>
#include <math.h>

#define SEQ  4096
#define EMB  2048
#define NH   16
#define NKVH 4
#define HD   128
#define WIN  2048
#define QDIM (NH*HD)    /* 2048 */
#define KVDIM (NKVH*HD) /* 512  */

// -------- scratch (device globals; no allocations allowed) --------
__device__ float g_q  [SEQ * QDIM];   // 32 MB
__device__ float g_k  [SEQ * KVDIM];  //  8 MB
__device__ float g_v  [SEQ * KVDIM];  //  8 MB
__device__ float g_att[SEQ * QDIM];   // 32 MB

// =====================================================================
// fp32 tiled GEMM: C[M,N] = A[M,K] @ B[K,N], row-major, dims % 128 == 0
// BM=BN=128, BK=16, 256 threads, 8x8 per-thread microtile
// =====================================================================
__global__ __launch_bounds__(256) void gemm_f32(
    const float* __restrict__ A, const float* __restrict__ B,
    float* __restrict__ C, int M, int N, int K)
{
    __shared__ float As[16][132];   // transposed A tile, padded
    __shared__ float Bs[16][128];

    const int tid = threadIdx.x;
    const int bm = blockIdx.y * 128;
    const int bn = blockIdx.x * 128;

    const int tx = tid & 15;   // n dim
    const int ty = tid >> 4;   // m dim

    float acc[8][8];
#pragma unroll
    for (int i = 0; i < 8; i++)
#pragma unroll
        for (int j = 0; j < 8; j++) acc[i][j] = 0.f;

    const int a_row = tid >> 2;        // 0..63
    const int a_kc  = (tid & 3) * 4;   // 0,4,8,12
    const int b_row = tid >> 5;        // 0..7
    const int b_col = (tid & 31) * 4;

    const float* Aptr = A + (size_t)bm * K;
    const float* Bptr = B + bn;

    for (int k0 = 0; k0 < K; k0 += 16) {
#pragma unroll
        for (int p = 0; p < 2; p++) {
            float4 av = *(const float4*)(Aptr + (size_t)(a_row + p*64) * K + k0 + a_kc);
            As[a_kc+0][a_row + p*64] = av.x;
            As[a_kc+1][a_row + p*64] = av.y;
            As[a_kc+2][a_row + p*64] = av.z;
            As[a_kc+3][a_row + p*64] = av.w;
            float4 bv = *(const float4*)(Bptr + (size_t)(k0 + b_row + p*8) * N + b_col);
            *(float4*)&Bs[b_row + p*8][b_col] = bv;
        }
        __syncthreads();
#pragma unroll
        for (int kk = 0; kk < 16; kk++) {
            float a[8], b[8];
            *(float4*)&a[0] = *(const float4*)&As[kk][ty*4];
            *(float4*)&a[4] = *(const float4*)&As[kk][64 + ty*4];
            *(float4*)&b[0] = *(const float4*)&Bs[kk][tx*4];
            *(float4*)&b[4] = *(const float4*)&Bs[kk][64 + tx*4];
#pragma unroll
            for (int i = 0; i < 8; i++)
#pragma unroll
                for (int j = 0; j < 8; j++)
                    acc[i][j] += a[i] * b[j];
        }
        __syncthreads();
    }

#pragma unroll
    for (int im = 0; im < 8; im++) {
        int m = bm + ((im < 4) ? (ty*4 + im) : (64 + ty*4 + im - 4));
        float4 v0 = make_float4(acc[im][0], acc[im][1], acc[im][2], acc[im][3]);
        float4 v1 = make_float4(acc[im][4], acc[im][5], acc[im][6], acc[im][7]);
        *(float4*)&C[(size_t)m * N + bn + tx*4]      = v0;
        *(float4*)&C[(size_t)m * N + bn + 64 + tx*4] = v1;
    }
}

// =====================================================================
// RoPE in-place on q (16 heads) and k (4 heads). One block per position.
// position_ids may be int32 (JAX default: int64 silently downcast) or
// true int64. Probe the layout: for arange positions, word[1]==1 iff
// int32, word[1]==0 (high half of position 0) iff int64.
// =====================================================================
__global__ __launch_bounds__(256) void rope_kernel(
    const int* __restrict__ pos_w,
    float* __restrict__ q, float* __restrict__ k)
{
    const int s = blockIdx.x;
    const int tid = threadIdx.x;
    __shared__ float cs[64], sn[64];

    if (tid < 64) {
        bool is64 = (pos_w[1] == 0);
        int pi = is64 ? pos_w[2 * s] : pos_w[s];
        float p = (float)pi;
        float ex = (float)(2 * tid) / (float)HD;
        float inv = powf(10000.0f, -ex);
        float ang = p * inv;
        sincosf(ang, &sn[tid], &cs[tid]);
    }
    __syncthreads();

    // q: 16 heads x 64 pairs = 1024
    for (int idx = tid; idx < NH * 64; idx += 256) {
        int h = idx >> 6, d = idx & 63;
        float* base = q + (size_t)s * QDIM + h * HD;
        float x1 = base[d], x2 = base[d + 64];
        float c = cs[d], si = sn[d];
        base[d]      = x1 * c - x2 * si;
        base[d + 64] = x2 * c + x1 * si;
    }
    // k: 4 heads x 64 pairs
    for (int idx = tid; idx < NKVH * 64; idx += 256) {
        int h = idx >> 6, d = idx & 63;
        float* base = k + (size_t)s * KVDIM + h * HD;
        float x1 = base[d], x2 = base[d + 64];
        float c = cs[d], si = sn[d];
        base[d]      = x1 * c - x2 * si;
        base[d + 64] = x2 * c + x1 * si;
    }
}

// =====================================================================
// Flash attention, fp32, sliding-window causal (j<=i && j>=i-WIN).
// Q tile: 64 rows per CTA. Key blocks of 32, chunks of 16.
// 256 threads: 4 threads per query row; thread 'quad' owns interleaved
// float4 granules g = quad + 4*i (i=0..7) of the 128-dim.
// =====================================================================
__global__ __launch_bounds__(256) void attn_kernel(
    const float* __restrict__ Q, const float* __restrict__ K,
    const float* __restrict__ V, float* __restrict__ O)
{
    __shared__ float Ks[32 * 128];  // 16 KB
    __shared__ float Vs[32 * 128];  // 16 KB

    const int tid  = threadIdx.x;
    const int qb   = blockIdx.x;     // 0..63
    const int h    = blockIdx.y;     // 0..15
    const int kvh  = h >> 2;
    const int r    = tid >> 2;       // 0..63
    const int quad = tid & 3;
    const int i_glob = qb * 64 + r;

    const float scale = 0.08838834764831845f; // 1/sqrt(128)

    float4 q4[8];
    {
        const float4* qrow = (const float4*)(Q + (size_t)i_glob * QDIM + h * HD);
#pragma unroll
        for (int i = 0; i < 8; i++) {
            float4 t = qrow[quad + 4*i];
            t.x *= scale; t.y *= scale; t.z *= scale; t.w *= scale;
            q4[i] = t;
        }
    }

    float4 o4[8];
#pragma unroll
    for (int i = 0; i < 8; i++) o4[i] = make_float4(0.f, 0.f, 0.f, 0.f);
    float m = -1e30f, l = 0.f;

    const int kb_start = max(0, qb * 2 - 64);  // WIN/32 = 64
    const int kb_end   = qb * 2 + 1;           // inclusive

    const float4* Ks4 = (const float4*)Ks;
    const float4* Vs4 = (const float4*)Vs;

    for (int kb = kb_start; kb <= kb_end; kb++) {
        __syncthreads();   // previous chunk's V reads done
        {
            const float4* ksrc = (const float4*)(K + (size_t)(kb*32) * KVDIM + kvh * HD);
            const float4* vsrc = (const float4*)(V + (size_t)(kb*32) * KVDIM + kvh * HD);
#pragma unroll
            for (int t = 0; t < 4; t++) {
                int idx = tid + t * 256;       // 0..1023 float4 slots
                int j = idx >> 5, w = idx & 31;
                ((float4*)Ks)[idx] = ksrc[j * 128 + w];
                ((float4*)Vs)[idx] = vsrc[j * 128 + w];
            }
        }
        __syncthreads();

#pragma unroll 1
        for (int ch = 0; ch < 2; ch++) {
            float s[16];
#pragma unroll
            for (int jj = 0; jj < 16; jj++) {
                const int j = ch * 16 + jj;
                float4 a = make_float4(0.f, 0.f, 0.f, 0.f);
#pragma unroll
                for (int i = 0; i < 8; i++) {
                    float4 kv = Ks4[j * 32 + quad + 4*i];
                    a.x += q4[i].x * kv.x;  a.y += q4[i].y * kv.y;
                    a.z += q4[i].z * kv.z;  a.w += q4[i].w * kv.w;
                }
                s[jj] = (a.x + a.y) + (a.z + a.w);
            }
            // sum partial dots across the 4 quad lanes of this row
#pragma unroll
            for (int jj = 0; jj < 16; jj++) {
                s[jj] += __shfl_xor_sync(0xffffffffu, s[jj], 1);
                s[jj] += __shfl_xor_sync(0xffffffffu, s[jj], 2);
            }
            // mask + chunk max
            float cmax = -1e30f;
#pragma unroll
            for (int jj = 0; jj < 16; jj++) {
                int j_glob = kb * 32 + ch * 16 + jj;
                bool valid = ((unsigned)(i_glob - j_glob)) <= (unsigned)WIN;
                s[jj] = valid ? s[jj] : -1e30f;
                cmax = fmaxf(cmax, s[jj]);
            }
            float m_new = fmaxf(m, cmax);
            float alpha = __expf(m - m_new);
            l *= alpha;
#pragma unroll
            for (int i = 0; i < 8; i++) {
                o4[i].x *= alpha; o4[i].y *= alpha;
                o4[i].z *= alpha; o4[i].w *= alpha;
            }
            m = m_new;

            float p[16];
#pragma unroll
            for (int jj = 0; jj < 16; jj++) {
                p[jj] = __expf(s[jj] - m_new);
                l += p[jj];
            }
#pragma unroll
            for (int jj = 0; jj < 16; jj++) {
                const int j = ch * 16 + jj;
#pragma unroll
                for (int i = 0; i < 8; i++) {
                    float4 vv = Vs4[j * 32 + quad + 4*i];
                    o4[i].x += p[jj] * vv.x;  o4[i].y += p[jj] * vv.y;
                    o4[i].z += p[jj] * vv.z;  o4[i].w += p[jj] * vv.w;
                }
            }
        }
    }

    const float inv_l = 1.0f / l;
    float4* orow = (float4*)(O + (size_t)i_glob * QDIM + h * HD);
#pragma unroll
    for (int i = 0; i < 8; i++) {
        float4 t = o4[i];
        t.x *= inv_l; t.y *= inv_l; t.z *= inv_l; t.w *= inv_l;
        orow[quad + 4*i] = t;
    }
}

// =====================================================================
extern "C" void kernel_launch(void* const* d_in, const int* in_sizes, int n_in,
                              void* d_out, int out_size)
{
    const float* query = (const float*)d_in[0];
    const float* key   = (const float*)d_in[1];
    const float* value = (const float*)d_in[2];
    const int*   pos   = (const int*)d_in[3];   // int32 words (handles int64 too)
    const float* wq    = (const float*)d_in[4];
    const float* wk    = (const float*)d_in[5];
    const float* wv    = (const float*)d_in[6];
    const float* wo    = (const float*)d_in[7];
    float*       out   = (float*)d_out;

    float *q_s, *k_s, *v_s, *att_s;
    cudaGetSymbolAddress((void**)&q_s,   g_q);
    cudaGetSymbolAddress((void**)&k_s,   g_k);
    cudaGetSymbolAddress((void**)&v_s,   g_v);
    cudaGetSymbolAddress((void**)&att_s, g_att);

    dim3 blk(256);

    // projections
    gemm_f32<<<dim3(QDIM/128,  SEQ/128), blk>>>(query, wq, q_s, SEQ, QDIM,  EMB);
    gemm_f32<<<dim3(KVDIM/128, SEQ/128), blk>>>(key,   wk, k_s, SEQ, KVDIM, EMB);
    gemm_f32<<<dim3(KVDIM/128, SEQ/128), blk>>>(value, wv, v_s, SEQ, KVDIM, EMB);

    // rope on q and k
    rope_kernel<<<SEQ, blk>>>(pos, q_s, k_s);

    // attention
    attn_kernel<<<dim3(SEQ/64, NH), blk>>>(q_s, k_s, v_s, att_s);

    // output projection
    gemm_f32<<<dim3(EMB/128, SEQ/128), blk>>>(att_s, wo, out, SEQ, EMB, QDIM);
}

// round 3
// speedup vs baseline: 1.2208x; 1.2208x over previous
#include <cuda_runtime.h>
#include <cuda_bf16.h>
#include <math.h>

#define SEQ  4096
#define EMB  2048
#define NH   16
#define NKVH 4
#define HD   128
#define WIN  2048
#define QDIM (NH*HD)    /* 2048 */
#define KVDIM (NKVH*HD) /* 512  */

// -------- scratch (device globals; no allocations allowed) --------
__device__ float g_q  [SEQ * QDIM];   // 32 MB
__device__ float g_k  [SEQ * KVDIM];  //  8 MB
__device__ float g_v  [SEQ * KVDIM];  //  8 MB
__device__ float g_att[SEQ * QDIM];   // 32 MB

// ---------------- PTX helpers ----------------
#define LDSM_X4(r0,r1,r2,r3,addr) \
  asm volatile("ldmatrix.sync.aligned.m8n8.x4.shared.b16 {%0,%1,%2,%3}, [%4];" \
    : "=r"(r0),"=r"(r1),"=r"(r2),"=r"(r3) : "r"(addr))

#define LDSM_X4_T(r0,r1,r2,r3,addr) \
  asm volatile("ldmatrix.sync.aligned.m8n8.x4.trans.shared.b16 {%0,%1,%2,%3}, [%4];" \
    : "=r"(r0),"=r"(r1),"=r"(r2),"=r"(r3) : "r"(addr))

#define MMA16816(c, a0,a1,a2,a3, b0,b1) \
  asm volatile("mma.sync.aligned.m16n8k16.row.col.f32.bf16.bf16.f32 " \
    "{%0,%1,%2,%3}, {%4,%5,%6,%7}, {%8,%9}, {%0,%1,%2,%3};" \
    : "+f"((c)[0]),"+f"((c)[1]),"+f"((c)[2]),"+f"((c)[3]) \
    : "r"(a0),"r"(a1),"r"(a2),"r"(a3),"r"(b0),"r"(b1))

__device__ __forceinline__ unsigned pack_bf2(__nv_bfloat16 lo16, __nv_bfloat16 hi16) {
    return ((unsigned)__bfloat16_as_ushort(hi16) << 16) | (unsigned)__bfloat16_as_ushort(lo16);
}

// split x into hi + lo bf16 pair (x2 packed for two consecutive elems)
__device__ __forceinline__ void split2(float x0, float x1, unsigned& hi, unsigned& lo) {
    __nv_bfloat16 h0 = __float2bfloat16(x0);
    __nv_bfloat16 h1 = __float2bfloat16(x1);
    __nv_bfloat16 l0 = __float2bfloat16(x0 - __bfloat162float(h0));
    __nv_bfloat16 l1 = __float2bfloat16(x1 - __bfloat162float(h1));
    hi = pack_bf2(h0, h1);
    lo = pack_bf2(l0, l1);
}

// =====================================================================
// split-bf16 GEMM: C[M,N] = A[M,K] @ B[K,N], fp32 in/out, ~fp32 accuracy
// A = Ah + Al (bf16), B = Bh + Bl; C ≈ Ah·Bh + Ah·Bl + Al·Bh.
// BM=BN=128, BK=32, 256 threads, warps in 2(m) x 4(n), warp tile 64x32.
// =====================================================================
#define A_STRIDE 40    /* 32 + 8 pad, bf16 elems: row stride 80B, ldmatrix conflict-free */
#define B_STRIDE 136   /* 128 + 8 pad */

__global__ __launch_bounds__(256) void gemm_bf16split(
    const float* __restrict__ A, const float* __restrict__ B,
    float* __restrict__ C, int M, int N, int K)
{
    __shared__ __nv_bfloat16 Ash[128 * A_STRIDE];
    __shared__ __nv_bfloat16 Asl[128 * A_STRIDE];
    __shared__ __nv_bfloat16 Bsh[32 * B_STRIDE];
    __shared__ __nv_bfloat16 Bsl[32 * B_STRIDE];

    const int tid  = threadIdx.x;
    const int warp = tid >> 5;
    const int lane = tid & 31;
    const int wm   = warp >> 2;     // 0..1
    const int wn   = warp & 3;      // 0..3
    const int bm   = blockIdx.y * 128;
    const int bn   = blockIdx.x * 128;

    float acc[4][4][4];
#pragma unroll
    for (int i = 0; i < 4; i++)
#pragma unroll
        for (int j = 0; j < 4; j++)
#pragma unroll
            for (int r = 0; r < 4; r++) acc[i][j][r] = 0.f;

    // gmem tile load indices
    const int am  = tid >> 3;          // 0..31 (+32*p)
    const int ak  = (tid & 7) * 4;     // 0..28
    const int bk  = tid >> 5;          // 0..7 (+8*p)
    const int bn4 = (tid & 31) * 4;    // 0..124

    const unsigned ash = (unsigned)__cvta_generic_to_shared(Ash);
    const unsigned asl = (unsigned)__cvta_generic_to_shared(Asl);
    const unsigned bsh = (unsigned)__cvta_generic_to_shared(Bsh);
    const unsigned bsl = (unsigned)__cvta_generic_to_shared(Bsl);

    float4 pa[4], pb[4];
#pragma unroll
    for (int p = 0; p < 4; p++) {
        pa[p] = *(const float4*)(A + (size_t)(bm + am + 32*p) * K + ak);
        pb[p] = *(const float4*)(B + (size_t)(bk + 8*p) * N + bn + bn4);
    }

    const int niter = K / 32;
    for (int it = 0; it < niter; it++) {
        // ---- stage current tile (split) into smem ----
#pragma unroll
        for (int p = 0; p < 4; p++) {
            unsigned h0, l0, h1, l1;
            split2(pa[p].x, pa[p].y, h0, l0);
            split2(pa[p].z, pa[p].w, h1, l1);
            int ai = (am + 32*p) * A_STRIDE + ak;
            *(unsigned*)&Ash[ai]   = h0;  *(unsigned*)&Ash[ai+2] = h1;
            *(unsigned*)&Asl[ai]   = l0;  *(unsigned*)&Asl[ai+2] = l1;
            split2(pb[p].x, pb[p].y, h0, l0);
            split2(pb[p].z, pb[p].w, h1, l1);
            int bi = (bk + 8*p) * B_STRIDE + bn4;
            *(unsigned*)&Bsh[bi]   = h0;  *(unsigned*)&Bsh[bi+2] = h1;
            *(unsigned*)&Bsl[bi]   = l0;  *(unsigned*)&Bsl[bi+2] = l1;
        }
        __syncthreads();

        // ---- prefetch next tile into registers ----
        if (it + 1 < niter) {
            int k0 = (it + 1) * 32;
#pragma unroll
            for (int p = 0; p < 4; p++) {
                pa[p] = *(const float4*)(A + (size_t)(bm + am + 32*p) * K + k0 + ak);
                pb[p] = *(const float4*)(B + (size_t)(k0 + bk + 8*p) * N + bn + bn4);
            }
        }

        // ---- compute on staged tile: 2 k-steps of 16 ----
#pragma unroll
        for (int ks = 0; ks < 32; ks += 16) {
            unsigned ah[4][4], al[4][4];
#pragma unroll
            for (int mi = 0; mi < 4; mi++) {
                unsigned off = 2u * ((unsigned)((wm*64 + mi*16 + (lane & 15)) * A_STRIDE
                                               + ks + (lane >> 4) * 8));
                LDSM_X4(ah[mi][0], ah[mi][1], ah[mi][2], ah[mi][3], ash + off);
                LDSM_X4(al[mi][0], al[mi][1], al[mi][2], al[mi][3], asl + off);
            }
            unsigned bh[4][2], bl[4][2];
#pragma unroll
            for (int nb = 0; nb < 2; nb++) {
                unsigned off = 2u * ((unsigned)((ks + (lane & 15)) * B_STRIDE
                                               + wn*32 + nb*16 + (lane >> 4) * 8));
                unsigned r0, r1, r2, r3;
                LDSM_X4_T(r0, r1, r2, r3, bsh + off);
                bh[2*nb][0] = r0; bh[2*nb][1] = r1;
                bh[2*nb+1][0] = r2; bh[2*nb+1][1] = r3;
                LDSM_X4_T(r0, r1, r2, r3, bsl + off);
                bl[2*nb][0] = r0; bl[2*nb][1] = r1;
                bl[2*nb+1][0] = r2; bl[2*nb+1][1] = r3;
            }
#pragma unroll
            for (int mi = 0; mi < 4; mi++) {
#pragma unroll
                for (int ni = 0; ni < 4; ni++) {
                    MMA16816(acc[mi][ni], ah[mi][0],ah[mi][1],ah[mi][2],ah[mi][3],
                             bh[ni][0], bh[ni][1]);
                    MMA16816(acc[mi][ni], ah[mi][0],ah[mi][1],ah[mi][2],ah[mi][3],
                             bl[ni][0], bl[ni][1]);
                    MMA16816(acc[mi][ni], al[mi][0],al[mi][1],al[mi][2],al[mi][3],
                             bh[ni][0], bh[ni][1]);
                }
            }
        }
        __syncthreads();
    }

    // ---- epilogue ----
    const int g = lane >> 2, q = lane & 3;
#pragma unroll
    for (int mi = 0; mi < 4; mi++) {
#pragma unroll
        for (int ni = 0; ni < 4; ni++) {
            int row = bm + wm*64 + mi*16 + g;
            int col = bn + wn*32 + ni*8 + q*2;
            *(float2*)&C[(size_t)row * N + col]       = make_float2(acc[mi][ni][0], acc[mi][ni][1]);
            *(float2*)&C[(size_t)(row + 8) * N + col] = make_float2(acc[mi][ni][2], acc[mi][ni][3]);
        }
    }
}

// =====================================================================
// RoPE in-place on q (16 heads) and k (4 heads). One block per position.
// position_ids arrive as int32 words (JAX x64-disabled downcast); probe
// handles true int64 too.
// =====================================================================
__global__ __launch_bounds__(256) void rope_kernel(
    const int* __restrict__ pos_w,
    float* __restrict__ q, float* __restrict__ k)
{
    const int s = blockIdx.x;
    const int tid = threadIdx.x;
    __shared__ float cs[64], sn[64];

    if (tid < 64) {
        bool is64 = (pos_w[1] == 0);
        int pi = is64 ? pos_w[2 * s] : pos_w[s];
        float p = (float)pi;
        float ex = (float)(2 * tid) / (float)HD;
        float inv = powf(10000.0f, -ex);
        float ang = p * inv;
        sincosf(ang, &sn[tid], &cs[tid]);
    }
    __syncthreads();

    for (int idx = tid; idx < NH * 64; idx += 256) {
        int h = idx >> 6, d = idx & 63;
        float* base = q + (size_t)s * QDIM + h * HD;
        float x1 = base[d], x2 = base[d + 64];
        float c = cs[d], si = sn[d];
        base[d]      = x1 * c - x2 * si;
        base[d + 64] = x2 * c + x1 * si;
    }
    for (int idx = tid; idx < NKVH * 64; idx += 256) {
        int h = idx >> 6, d = idx & 63;
        float* base = k + (size_t)s * KVDIM + h * HD;
        float x1 = base[d], x2 = base[d + 64];
        float c = cs[d], si = sn[d];
        base[d]      = x1 * c - x2 * si;
        base[d + 64] = x2 * c + x1 * si;
    }
}

// =====================================================================
// Flash attention, fp32, sliding-window causal (j<=i && j>=i-WIN).
// =====================================================================
__global__ __launch_bounds__(256) void attn_kernel(
    const float* __restrict__ Q, const float* __restrict__ K,
    const float* __restrict__ V, float* __restrict__ O)
{
    __shared__ float Ks[32 * 128];
    __shared__ float Vs[32 * 128];

    const int tid  = threadIdx.x;
    const int qb   = blockIdx.x;
    const int h    = blockIdx.y;
    const int kvh  = h >> 2;
    const int r    = tid >> 2;
    const int quad = tid & 3;
    const int i_glob = qb * 64 + r;

    const float scale = 0.08838834764831845f;

    float4 q4[8];
    {
        const float4* qrow = (const float4*)(Q + (size_t)i_glob * QDIM + h * HD);
#pragma unroll
        for (int i = 0; i < 8; i++) {
            float4 t = qrow[quad + 4*i];
            t.x *= scale; t.y *= scale; t.z *= scale; t.w *= scale;
            q4[i] = t;
        }
    }

    float4 o4[8];
#pragma unroll
    for (int i = 0; i < 8; i++) o4[i] = make_float4(0.f, 0.f, 0.f, 0.f);
    float m = -1e30f, l = 0.f;

    const int kb_start = max(0, qb * 2 - 64);
    const int kb_end   = qb * 2 + 1;

    const float4* Ks4 = (const float4*)Ks;
    const float4* Vs4 = (const float4*)Vs;

    for (int kb = kb_start; kb <= kb_end; kb++) {
        __syncthreads();
        {
            const float4* ksrc = (const float4*)(K + (size_t)(kb*32) * KVDIM + kvh * HD);
            const float4* vsrc = (const float4*)(V + (size_t)(kb*32) * KVDIM + kvh * HD);
#pragma unroll
            for (int t = 0; t < 4; t++) {
                int idx = tid + t * 256;
                int j = idx >> 5, w = idx & 31;
                ((float4*)Ks)[idx] = ksrc[j * 128 + w];
                ((float4*)Vs)[idx] = vsrc[j * 128 + w];
            }
        }
        __syncthreads();

#pragma unroll 1
        for (int ch = 0; ch < 2; ch++) {
            float s[16];
#pragma unroll
            for (int jj = 0; jj < 16; jj++) {
                const int j = ch * 16 + jj;
                float4 a = make_float4(0.f, 0.f, 0.f, 0.f);
#pragma unroll
                for (int i = 0; i < 8; i++) {
                    float4 kv = Ks4[j * 32 + quad + 4*i];
                    a.x += q4[i].x * kv.x;  a.y += q4[i].y * kv.y;
                    a.z += q4[i].z * kv.z;  a.w += q4[i].w * kv.w;
                }
                s[jj] = (a.x + a.y) + (a.z + a.w);
            }
#pragma unroll
            for (int jj = 0; jj < 16; jj++) {
                s[jj] += __shfl_xor_sync(0xffffffffu, s[jj], 1);
                s[jj] += __shfl_xor_sync(0xffffffffu, s[jj], 2);
            }
            float cmax = -1e30f;
#pragma unroll
            for (int jj = 0; jj < 16; jj++) {
                int j_glob = kb * 32 + ch * 16 + jj;
                bool valid = ((unsigned)(i_glob - j_glob)) <= (unsigned)WIN;
                s[jj] = valid ? s[jj] : -1e30f;
                cmax = fmaxf(cmax, s[jj]);
            }
            float m_new = fmaxf(m, cmax);
            float alpha = __expf(m - m_new);
            l *= alpha;
#pragma unroll
            for (int i = 0; i < 8; i++) {
                o4[i].x *= alpha; o4[i].y *= alpha;
                o4[i].z *= alpha; o4[i].w *= alpha;
            }
            m = m_new;

            float p[16];
#pragma unroll
            for (int jj = 0; jj < 16; jj++) {
                p[jj] = __expf(s[jj] - m_new);
                l += p[jj];
            }
#pragma unroll
            for (int jj = 0; jj < 16; jj++) {
                const int j = ch * 16 + jj;
#pragma unroll
                for (int i = 0; i < 8; i++) {
                    float4 vv = Vs4[j * 32 + quad + 4*i];
                    o4[i].x += p[jj] * vv.x;  o4[i].y += p[jj] * vv.y;
                    o4[i].z += p[jj] * vv.z;  o4[i].w += p[jj] * vv.w;
                }
            }
        }
    }

    const float inv_l = 1.0f / l;
    float4* orow = (float4*)(O + (size_t)i_glob * QDIM + h * HD);
#pragma unroll
    for (int i = 0; i < 8; i++) {
        float4 t = o4[i];
        t.x *= inv_l; t.y *= inv_l; t.z *= inv_l; t.w *= inv_l;
        orow[quad + 4*i] = t;
    }
}

// =====================================================================
extern "C" void kernel_launch(void* const* d_in, const int* in_sizes, int n_in,
                              void* d_out, int out_size)
{
    const float* query = (const float*)d_in[0];
    const float* key   = (const float*)d_in[1];
    const float* value = (const float*)d_in[2];
    const int*   pos   = (const int*)d_in[3];
    const float* wq    = (const float*)d_in[4];
    const float* wk    = (const float*)d_in[5];
    const float* wv    = (const float*)d_in[6];
    const float* wo    = (const float*)d_in[7];
    float*       out   = (float*)d_out;

    float *q_s, *k_s, *v_s, *att_s;
    cudaGetSymbolAddress((void**)&q_s,   g_q);
    cudaGetSymbolAddress((void**)&k_s,   g_k);
    cudaGetSymbolAddress((void**)&v_s,   g_v);
    cudaGetSymbolAddress((void**)&att_s, g_att);

    dim3 blk(256);

    gemm_bf16split<<<dim3(QDIM/128,  SEQ/128), blk>>>(query, wq, q_s, SEQ, QDIM,  EMB);
    gemm_bf16split<<<dim3(KVDIM/128, SEQ/128), blk>>>(key,   wk, k_s, SEQ, KVDIM, EMB);
    gemm_bf16split<<<dim3(KVDIM/128, SEQ/128), blk>>>(value, wv, v_s, SEQ, KVDIM, EMB);

    rope_kernel<<<SEQ, blk>>>(pos, q_s, k_s);

    attn_kernel<<<dim3(SEQ/64, NH), blk>>>(q_s, k_s, v_s, att_s);

    gemm_bf16split<<<dim3(EMB/128, SEQ/128), blk>>>(att_s, wo, out, SEQ, EMB, QDIM);
}

// round 5
// speedup vs baseline: 3.2182x; 2.6362x over previous
#include <cuda_runtime.h>
#include <cuda_bf16.h>
#include <math.h>

#define SEQ  4096
#define EMB  2048
#define NH   16
#define NKVH 4
#define HD   128
#define WIN  2048
#define QDIM (NH*HD)    /* 2048 */
#define KVDIM (NKVH*HD) /* 512  */

// -------- scratch (device globals; no allocations allowed) --------
__device__ float g_q  [SEQ * QDIM];   // 32 MB
__device__ float g_k  [SEQ * KVDIM];  //  8 MB
__device__ float g_v  [SEQ * KVDIM];  //  8 MB
__device__ float g_att[SEQ * QDIM];   // 32 MB

// ---------------- PTX helpers ----------------
#define LDSM_X4(r0,r1,r2,r3,addr) \
  asm volatile("ldmatrix.sync.aligned.m8n8.x4.shared.b16 {%0,%1,%2,%3}, [%4];" \
    : "=r"(r0),"=r"(r1),"=r"(r2),"=r"(r3) : "r"(addr))

#define LDSM_X4_T(r0,r1,r2,r3,addr) \
  asm volatile("ldmatrix.sync.aligned.m8n8.x4.trans.shared.b16 {%0,%1,%2,%3}, [%4];" \
    : "=r"(r0),"=r"(r1),"=r"(r2),"=r"(r3) : "r"(addr))

#define MMA16816(c, a0,a1,a2,a3, b0,b1) \
  asm volatile("mma.sync.aligned.m16n8k16.row.col.f32.bf16.bf16.f32 " \
    "{%0,%1,%2,%3}, {%4,%5,%6,%7}, {%8,%9}, {%0,%1,%2,%3};" \
    : "+f"((c)[0]),"+f"((c)[1]),"+f"((c)[2]),"+f"((c)[3]) \
    : "r"(a0),"r"(a1),"r"(a2),"r"(a3),"r"(b0),"r"(b1))

__device__ __forceinline__ unsigned pack_bf2(__nv_bfloat16 lo16, __nv_bfloat16 hi16) {
    return ((unsigned)__bfloat16_as_ushort(hi16) << 16) | (unsigned)__bfloat16_as_ushort(lo16);
}

__device__ __forceinline__ void split2(float x0, float x1, unsigned& hi, unsigned& lo) {
    __nv_bfloat16 h0 = __float2bfloat16(x0);
    __nv_bfloat16 h1 = __float2bfloat16(x1);
    __nv_bfloat16 l0 = __float2bfloat16(x0 - __bfloat162float(h0));
    __nv_bfloat16 l1 = __float2bfloat16(x1 - __bfloat162float(h1));
    hi = pack_bf2(h0, h1);
    lo = pack_bf2(l0, l1);
}

// =====================================================================
// split-bf16 GEMM; z selects (A,B,C) set so K and V projections batch
// into a single launch.
// =====================================================================
#define A_STRIDE 40
#define B_STRIDE 136

__global__ __launch_bounds__(256) void gemm_bf16split(
    const float* __restrict__ A0, const float* __restrict__ A1,
    const float* __restrict__ B0, const float* __restrict__ B1,
    float* __restrict__ C0, float* __restrict__ C1, int M, int N, int K)
{
    const float* A = (blockIdx.z == 0) ? A0 : A1;
    const float* B = (blockIdx.z == 0) ? B0 : B1;
    float*       C = (blockIdx.z == 0) ? C0 : C1;

    __shared__ __nv_bfloat16 Ash[128 * A_STRIDE];
    __shared__ __nv_bfloat16 Asl[128 * A_STRIDE];
    __shared__ __nv_bfloat16 Bsh[32 * B_STRIDE];
    __shared__ __nv_bfloat16 Bsl[32 * B_STRIDE];

    const int tid  = threadIdx.x;
    const int warp = tid >> 5;
    const int lane = tid & 31;
    const int wm   = warp >> 2;
    const int wn   = warp & 3;
    const int bm   = blockIdx.y * 128;
    const int bn   = blockIdx.x * 128;

    float acc[4][4][4];
#pragma unroll
    for (int i = 0; i < 4; i++)
#pragma unroll
        for (int j = 0; j < 4; j++)
#pragma unroll
            for (int r = 0; r < 4; r++) acc[i][j][r] = 0.f;

    const int am  = tid >> 3;
    const int ak  = (tid & 7) * 4;
    const int bk  = tid >> 5;
    const int bn4 = (tid & 31) * 4;

    const unsigned ash = (unsigned)__cvta_generic_to_shared(Ash);
    const unsigned asl = (unsigned)__cvta_generic_to_shared(Asl);
    const unsigned bsh = (unsigned)__cvta_generic_to_shared(Bsh);
    const unsigned bsl = (unsigned)__cvta_generic_to_shared(Bsl);

    float4 pa[4], pb[4];
#pragma unroll
    for (int p = 0; p < 4; p++) {
        pa[p] = *(const float4*)(A + (size_t)(bm + am + 32*p) * K + ak);
        pb[p] = *(const float4*)(B + (size_t)(bk + 8*p) * N + bn + bn4);
    }

    const int niter = K / 32;
    for (int it = 0; it < niter; it++) {
#pragma unroll
        for (int p = 0; p < 4; p++) {
            unsigned h0, l0, h1, l1;
            split2(pa[p].x, pa[p].y, h0, l0);
            split2(pa[p].z, pa[p].w, h1, l1);
            int ai = (am + 32*p) * A_STRIDE + ak;
            *(unsigned*)&Ash[ai]   = h0;  *(unsigned*)&Ash[ai+2] = h1;
            *(unsigned*)&Asl[ai]   = l0;  *(unsigned*)&Asl[ai+2] = l1;
            split2(pb[p].x, pb[p].y, h0, l0);
            split2(pb[p].z, pb[p].w, h1, l1);
            int bi = (bk + 8*p) * B_STRIDE + bn4;
            *(unsigned*)&Bsh[bi]   = h0;  *(unsigned*)&Bsh[bi+2] = h1;
            *(unsigned*)&Bsl[bi]   = l0;  *(unsigned*)&Bsl[bi+2] = l1;
        }
        __syncthreads();

        if (it + 1 < niter) {
            int k0 = (it + 1) * 32;
#pragma unroll
            for (int p = 0; p < 4; p++) {
                pa[p] = *(const float4*)(A + (size_t)(bm + am + 32*p) * K + k0 + ak);
                pb[p] = *(const float4*)(B + (size_t)(k0 + bk + 8*p) * N + bn + bn4);
            }
        }

#pragma unroll
        for (int ks = 0; ks < 32; ks += 16) {
            unsigned ah[4][4], al[4][4];
#pragma unroll
            for (int mi = 0; mi < 4; mi++) {
                unsigned off = 2u * ((unsigned)((wm*64 + mi*16 + (lane & 15)) * A_STRIDE
                                               + ks + (lane >> 4) * 8));
                LDSM_X4(ah[mi][0], ah[mi][1], ah[mi][2], ah[mi][3], ash + off);
                LDSM_X4(al[mi][0], al[mi][1], al[mi][2], al[mi][3], asl + off);
            }
            unsigned bh[4][2], bl[4][2];
#pragma unroll
            for (int nb = 0; nb < 2; nb++) {
                unsigned off = 2u * ((unsigned)((ks + (lane & 15)) * B_STRIDE
                                               + wn*32 + nb*16 + (lane >> 4) * 8));
                unsigned r0, r1, r2, r3;
                LDSM_X4_T(r0, r1, r2, r3, bsh + off);
                bh[2*nb][0] = r0; bh[2*nb][1] = r1;
                bh[2*nb+1][0] = r2; bh[2*nb+1][1] = r3;
                LDSM_X4_T(r0, r1, r2, r3, bsl + off);
                bl[2*nb][0] = r0; bl[2*nb][1] = r1;
                bl[2*nb+1][0] = r2; bl[2*nb+1][1] = r3;
            }
#pragma unroll
            for (int mi = 0; mi < 4; mi++) {
#pragma unroll
                for (int ni = 0; ni < 4; ni++) {
                    MMA16816(acc[mi][ni], ah[mi][0],ah[mi][1],ah[mi][2],ah[mi][3],
                             bh[ni][0], bh[ni][1]);
                    MMA16816(acc[mi][ni], ah[mi][0],ah[mi][1],ah[mi][2],ah[mi][3],
                             bl[ni][0], bl[ni][1]);
                    MMA16816(acc[mi][ni], al[mi][0],al[mi][1],al[mi][2],al[mi][3],
                             bh[ni][0], bh[ni][1]);
                }
            }
        }
        __syncthreads();
    }

    const int g = lane >> 2, q = lane & 3;
#pragma unroll
    for (int mi = 0; mi < 4; mi++) {
#pragma unroll
        for (int ni = 0; ni < 4; ni++) {
            int row = bm + wm*64 + mi*16 + g;
            int col = bn + wn*32 + ni*8 + q*2;
            *(float2*)&C[(size_t)row * N + col]       = make_float2(acc[mi][ni][0], acc[mi][ni][1]);
            *(float2*)&C[(size_t)(row + 8) * N + col] = make_float2(acc[mi][ni][2], acc[mi][ni][3]);
        }
    }
}

// =====================================================================
// RoPE (position_ids read as int32 words, int64 probe)
// =====================================================================
__global__ __launch_bounds__(256) void rope_kernel(
    const int* __restrict__ pos_w,
    float* __restrict__ q, float* __restrict__ k)
{
    const int s = blockIdx.x;
    const int tid = threadIdx.x;
    __shared__ float cs[64], sn[64];

    if (tid < 64) {
        bool is64 = (pos_w[1] == 0);
        int pi = is64 ? pos_w[2 * s] : pos_w[s];
        float p = (float)pi;
        float ex = (float)(2 * tid) / (float)HD;
        float inv = powf(10000.0f, -ex);
        float ang = p * inv;
        sincosf(ang, &sn[tid], &cs[tid]);
    }
    __syncthreads();

    for (int idx = tid; idx < NH * 64; idx += 256) {
        int h = idx >> 6, d = idx & 63;
        float* base = q + (size_t)s * QDIM + h * HD;
        float x1 = base[d], x2 = base[d + 64];
        float c = cs[d], si = sn[d];
        base[d]      = x1 * c - x2 * si;
        base[d + 64] = x2 * c + x1 * si;
    }
    for (int idx = tid; idx < NKVH * 64; idx += 256) {
        int h = idx >> 6, d = idx & 63;
        float* base = k + (size_t)s * KVDIM + h * HD;
        float x1 = base[d], x2 = base[d + 64];
        float c = cs[d], si = sn[d];
        base[d]      = x1 * c - x2 * si;
        base[d + 64] = x2 * c + x1 * si;
    }
}

// =====================================================================
// MMA flash attention. CTA: 8 warps, 128 q-rows, one head.
// K-blocks of 64 keys. split-bf16 for both QK^T and P*V.
// smem: qh,ql(32K) kh,kl,vh,vl(16K) = 128KB dynamic; XOR-swizzled rows.
// =====================================================================
#define SM_QH 0
#define SM_QL 32768
#define SM_KH 65536
#define SM_KL 81920
#define SM_VH 98304
#define SM_VL 114688
#define SMEM_ATTN 131072

__device__ __forceinline__ int swz(int row, int col_b16) {
    return row * 256 + ((((col_b16 >> 3) ^ (row & 7)) << 4)) + ((col_b16 & 7) << 1);
}

__global__ __launch_bounds__(256) void attn_mma(
    const float* __restrict__ Q, const float* __restrict__ K,
    const float* __restrict__ V, float* __restrict__ O)
{
    extern __shared__ char sm[];
    const unsigned smu = (unsigned)__cvta_generic_to_shared(sm);

    const int tid  = threadIdx.x;
    const int warp = tid >> 5;
    const int lane = tid & 31;
    const int g    = lane >> 2;
    const int qd   = lane & 3;
    const int qb   = blockIdx.x;
    const int h    = blockIdx.y;
    const int kvh  = h >> 2;
    const int i0   = qb * 128;

    const float QSCALE = (float)(1.4426950408889634 * 0.08838834764831845);

    // ---- stage Q (scaled, split) ----
#pragma unroll
    for (int rep = 0; rep < 16; rep++) {
        int e   = tid + rep * 256;
        int row = e >> 5;
        int c4  = (e & 31) * 4;
        float4 v4 = *(const float4*)(Q + (size_t)(i0 + row) * QDIM + h * HD + c4);
        v4.x *= QSCALE; v4.y *= QSCALE; v4.z *= QSCALE; v4.w *= QSCALE;
        unsigned h0, l0, h1, l1;
        split2(v4.x, v4.y, h0, l0);
        split2(v4.z, v4.w, h1, l1);
        int off = swz(row, c4);
        *(unsigned*)(sm + SM_QH + off)     = h0;
        *(unsigned*)(sm + SM_QH + off + 4) = h1;
        *(unsigned*)(sm + SM_QL + off)     = l0;
        *(unsigned*)(sm + SM_QL + off + 4) = l1;
    }

    float o[16][4];
#pragma unroll
    for (int i = 0; i < 16; i++)
#pragma unroll
        for (int c = 0; c < 4; c++) o[i][c] = 0.f;

    float m0 = -1e30f, m1 = -1e30f, l0s = 0.f, l1s = 0.f;

    const int ig0 = i0 + warp * 16 + g;
    const int ig1 = ig0 + 8;

    const int kb_lo = max(0, qb * 2 - 32);
    const int kb_hi = qb * 2 + 1;

    for (int kb = kb_lo; kb <= kb_hi; kb++) {
        __syncthreads();
#pragma unroll
        for (int rep = 0; rep < 8; rep++) {
            int e   = tid + rep * 256;
            int row = e >> 5;
            int c4  = (e & 31) * 4;
            int off = swz(row, c4);
            size_t src = (size_t)(kb * 64 + row) * KVDIM + kvh * HD + c4;
            float4 kv = *(const float4*)(K + src);
            unsigned h0, l0, h1, l1;
            split2(kv.x, kv.y, h0, l0);
            split2(kv.z, kv.w, h1, l1);
            *(unsigned*)(sm + SM_KH + off)     = h0;
            *(unsigned*)(sm + SM_KH + off + 4) = h1;
            *(unsigned*)(sm + SM_KL + off)     = l0;
            *(unsigned*)(sm + SM_KL + off + 4) = l1;
            float4 vv = *(const float4*)(V + src);
            split2(vv.x, vv.y, h0, l0);
            split2(vv.z, vv.w, h1, l1);
            *(unsigned*)(sm + SM_VH + off)     = h0;
            *(unsigned*)(sm + SM_VH + off + 4) = h1;
            *(unsigned*)(sm + SM_VL + off)     = l0;
            *(unsigned*)(sm + SM_VL + off + 4) = l1;
        }
        __syncthreads();

        float S[8][4];
#pragma unroll
        for (int i = 0; i < 8; i++)
#pragma unroll
            for (int c = 0; c < 4; c++) S[i][c] = 0.f;

#pragma unroll
        for (int kc = 0; kc < 8; kc++) {
            unsigned ah0,ah1,ah2,ah3, al0,al1,al2,al3;
            {
                int aoff = swz(warp*16 + (lane & 15), kc*16 + (lane >> 4) * 8);
                LDSM_X4(ah0,ah1,ah2,ah3, smu + SM_QH + aoff);
                LDSM_X4(al0,al1,al2,al3, smu + SM_QL + aoff);
            }
#pragma unroll
            for (int ntp = 0; ntp < 4; ntp++) {
                int boff = swz(ntp*16 + (lane & 15), kc*16 + (lane >> 4) * 8);
                unsigned k0,k1,k2,k3, e0,e1,e2,e3;
                LDSM_X4(k0,k1,k2,k3, smu + SM_KH + boff);
                LDSM_X4(e0,e1,e2,e3, smu + SM_KL + boff);
                MMA16816(S[2*ntp],   ah0,ah1,ah2,ah3, k0,k2);
                MMA16816(S[2*ntp],   ah0,ah1,ah2,ah3, e0,e2);
                MMA16816(S[2*ntp],   al0,al1,al2,al3, k0,k2);
                MMA16816(S[2*ntp+1], ah0,ah1,ah2,ah3, k1,k3);
                MMA16816(S[2*ntp+1], ah0,ah1,ah2,ah3, e1,e3);
                MMA16816(S[2*ntp+1], al0,al1,al2,al3, k1,k3);
            }
        }

        bool need_mask = (kb >= qb*2) || (kb <= qb*2 - 31);
        if (need_mask) {
#pragma unroll
            for (int nt = 0; nt < 8; nt++) {
                int j0 = kb*64 + nt*8 + 2*qd;
                S[nt][0] = ((unsigned)(ig0 - j0)     <= (unsigned)WIN) ? S[nt][0] : -1e30f;
                S[nt][1] = ((unsigned)(ig0 - j0 - 1) <= (unsigned)WIN) ? S[nt][1] : -1e30f;
                S[nt][2] = ((unsigned)(ig1 - j0)     <= (unsigned)WIN) ? S[nt][2] : -1e30f;
                S[nt][3] = ((unsigned)(ig1 - j0 - 1) <= (unsigned)WIN) ? S[nt][3] : -1e30f;
            }
        }

        float mx0 = -1e30f, mx1 = -1e30f;
#pragma unroll
        for (int nt = 0; nt < 8; nt++) {
            mx0 = fmaxf(mx0, fmaxf(S[nt][0], S[nt][1]));
            mx1 = fmaxf(mx1, fmaxf(S[nt][2], S[nt][3]));
        }
        mx0 = fmaxf(mx0, __shfl_xor_sync(0xffffffffu, mx0, 1));
        mx0 = fmaxf(mx0, __shfl_xor_sync(0xffffffffu, mx0, 2));
        mx1 = fmaxf(mx1, __shfl_xor_sync(0xffffffffu, mx1, 1));
        mx1 = fmaxf(mx1, __shfl_xor_sync(0xffffffffu, mx1, 2));

        float mn0 = fmaxf(m0, mx0);
        float mn1 = fmaxf(m1, mx1);
        float a0 = exp2f(m0 - mn0);
        float a1 = exp2f(m1 - mn1);
        float ok0 = (mn0 > -5e29f) ? 1.f : 0.f;
        float ok1 = (mn1 > -5e29f) ? 1.f : 0.f;
        m0 = mn0; m1 = mn1;
        l0s *= a0; l1s *= a1;

#pragma unroll
        for (int nt = 0; nt < 8; nt++) {
            S[nt][0] = exp2f(S[nt][0] - mn0) * ok0;
            S[nt][1] = exp2f(S[nt][1] - mn0) * ok0;
            S[nt][2] = exp2f(S[nt][2] - mn1) * ok1;
            S[nt][3] = exp2f(S[nt][3] - mn1) * ok1;
            l0s += S[nt][0] + S[nt][1];
            l1s += S[nt][2] + S[nt][3];
        }

#pragma unroll
        for (int i = 0; i < 16; i++) {
            o[i][0] *= a0; o[i][1] *= a0;
            o[i][2] *= a1; o[i][3] *= a1;
        }

        unsigned ph[4][4], pl[4][4];
#pragma unroll
        for (int t = 0; t < 4; t++) {
            split2(S[2*t][0],   S[2*t][1],   ph[t][0], pl[t][0]);
            split2(S[2*t][2],   S[2*t][3],   ph[t][1], pl[t][1]);
            split2(S[2*t+1][0], S[2*t+1][1], ph[t][2], pl[t][2]);
            split2(S[2*t+1][2], S[2*t+1][3], ph[t][3], pl[t][3]);
        }

#pragma unroll
        for (int t = 0; t < 4; t++) {
#pragma unroll
            for (int ntp = 0; ntp < 8; ntp++) {
                int voff = swz(t*16 + (lane & 15), ntp*16 + (lane >> 4) * 8);
                unsigned v0,v1,v2,v3, w0,w1,w2,w3;
                LDSM_X4_T(v0,v1,v2,v3, smu + SM_VH + voff);
                LDSM_X4_T(w0,w1,w2,w3, smu + SM_VL + voff);
                MMA16816(o[2*ntp],   ph[t][0],ph[t][1],ph[t][2],ph[t][3], v0,v1);
                MMA16816(o[2*ntp],   ph[t][0],ph[t][1],ph[t][2],ph[t][3], w0,w1);
                MMA16816(o[2*ntp],   pl[t][0],pl[t][1],pl[t][2],pl[t][3], v0,v1);
                MMA16816(o[2*ntp+1], ph[t][0],ph[t][1],ph[t][2],ph[t][3], v2,v3);
                MMA16816(o[2*ntp+1], ph[t][0],ph[t][1],ph[t][2],ph[t][3], w2,w3);
                MMA16816(o[2*ntp+1], pl[t][0],pl[t][1],pl[t][2],pl[t][3], v2,v3);
            }
        }
    }

    l0s += __shfl_xor_sync(0xffffffffu, l0s, 1);
    l0s += __shfl_xor_sync(0xffffffffu, l0s, 2);
    l1s += __shfl_xor_sync(0xffffffffu, l1s, 1);
    l1s += __shfl_xor_sync(0xffffffffu, l1s, 2);
    float inv0 = 1.f / l0s;
    float inv1 = 1.f / l1s;

#pragma unroll
    for (int nt = 0; nt < 16; nt++) {
        int col = h * HD + nt * 8 + 2 * qd;
        *(float2*)&O[(size_t)ig0 * QDIM + col] = make_float2(o[nt][0] * inv0, o[nt][1] * inv0);
        *(float2*)&O[(size_t)ig1 * QDIM + col] = make_float2(o[nt][2] * inv1, o[nt][3] * inv1);
    }
}

// =====================================================================
extern "C" void kernel_launch(void* const* d_in, const int* in_sizes, int n_in,
                              void* d_out, int out_size)
{
    const float* query = (const float*)d_in[0];
    const float* key   = (const float*)d_in[1];
    const float* value = (const float*)d_in[2];
    const int*   pos   = (const int*)d_in[3];
    const float* wq    = (const float*)d_in[4];
    const float* wk    = (const float*)d_in[5];
    const float* wv    = (const float*)d_in[6];
    const float* wo    = (const float*)d_in[7];
    float*       out   = (float*)d_out;

    float *q_s, *k_s, *v_s, *att_s;
    cudaGetSymbolAddress((void**)&q_s,   g_q);
    cudaGetSymbolAddress((void**)&k_s,   g_k);
    cudaGetSymbolAddress((void**)&v_s,   g_v);
    cudaGetSymbolAddress((void**)&att_s, g_att);

    cudaFuncSetAttribute(attn_mma, cudaFuncAttributeMaxDynamicSharedMemorySize, SMEM_ATTN);

    dim3 blk(256);

    gemm_bf16split<<<dim3(QDIM/128,  SEQ/128, 1), blk>>>(query, query, wq, wq, q_s, q_s, SEQ, QDIM,  EMB);
    gemm_bf16split<<<dim3(KVDIM/128, SEQ/128, 2), blk>>>(key,   value, wk, wv, k_s, v_s, SEQ, KVDIM, EMB);

    rope_kernel<<<SEQ, blk>>>(pos, q_s, k_s);

    attn_mma<<<dim3(SEQ/128, NH), blk, SMEM_ATTN>>>(q_s, k_s, v_s, att_s);

    gemm_bf16split<<<dim3(EMB/128, SEQ/128, 1), blk>>>(att_s, att_s, wo, wo, out, out, SEQ, EMB, QDIM);
}

// round 6
// speedup vs baseline: 3.8821x; 1.2063x over previous
#include <cuda_runtime.h>
#include <cuda_bf16.h>
#include <math.h>

#define SEQ  4096
#define EMB  2048
#define NH   16
#define NKVH 4
#define HD   128
#define WIN  2048
#define QDIM (NH*HD)    /* 2048 */
#define KVDIM (NKVH*HD) /* 512  */

// -------- scratch (device globals; no allocations allowed) --------
__device__ float g_q [SEQ * QDIM];    // q proj out (fp32, rope input)
__device__ float g_k [SEQ * KVDIM];   // k proj out (fp32, rope input)
__device__ __nv_bfloat16 g_qh[SEQ*QDIM],  g_ql[SEQ*QDIM];    // rope'd+scaled q split
__device__ __nv_bfloat16 g_kh[SEQ*KVDIM], g_kl[SEQ*KVDIM];   // rope'd k split
__device__ __nv_bfloat16 g_vh[SEQ*KVDIM], g_vl[SEQ*KVDIM];   // v proj split
__device__ __nv_bfloat16 g_ath[SEQ*QDIM], g_atl[SEQ*QDIM];   // attention out split
__device__ __nv_bfloat16 g_xqh[SEQ*EMB],  g_xql[SEQ*EMB];    // input splits
__device__ __nv_bfloat16 g_xkh[SEQ*EMB],  g_xkl[SEQ*EMB];
__device__ __nv_bfloat16 g_xvh[SEQ*EMB],  g_xvl[SEQ*EMB];
__device__ __nv_bfloat16 g_wqh[EMB*QDIM], g_wql[EMB*QDIM];   // weight splits
__device__ __nv_bfloat16 g_wkh[EMB*KVDIM],g_wkl[EMB*KVDIM];
__device__ __nv_bfloat16 g_wvh[EMB*KVDIM],g_wvl[EMB*KVDIM];
__device__ __nv_bfloat16 g_woh[QDIM*EMB], g_wol[QDIM*EMB];

// ---------------- PTX helpers ----------------
#define LDSM_X4(r0,r1,r2,r3,addr) \
  asm volatile("ldmatrix.sync.aligned.m8n8.x4.shared.b16 {%0,%1,%2,%3}, [%4];" \
    : "=r"(r0),"=r"(r1),"=r"(r2),"=r"(r3) : "r"(addr))

#define LDSM_X4_T(r0,r1,r2,r3,addr) \
  asm volatile("ldmatrix.sync.aligned.m8n8.x4.trans.shared.b16 {%0,%1,%2,%3}, [%4];" \
    : "=r"(r0),"=r"(r1),"=r"(r2),"=r"(r3) : "r"(addr))

#define MMA16816(c, a0,a1,a2,a3, b0,b1) \
  asm volatile("mma.sync.aligned.m16n8k16.row.col.f32.bf16.bf16.f32 " \
    "{%0,%1,%2,%3}, {%4,%5,%6,%7}, {%8,%9}, {%0,%1,%2,%3};" \
    : "+f"((c)[0]),"+f"((c)[1]),"+f"((c)[2]),"+f"((c)[3]) \
    : "r"(a0),"r"(a1),"r"(a2),"r"(a3),"r"(b0),"r"(b1))

#define CP_ASYNC16(dst32, srcptr) \
  asm volatile("cp.async.cg.shared.global [%0], [%1], 16;" :: "r"(dst32), "l"(srcptr))
#define CP_COMMIT() asm volatile("cp.async.commit_group;")
#define CP_WAIT0()  asm volatile("cp.async.wait_group 0;")

__device__ __forceinline__ unsigned pack_bf2(__nv_bfloat16 lo16, __nv_bfloat16 hi16) {
    return ((unsigned)__bfloat16_as_ushort(hi16) << 16) | (unsigned)__bfloat16_as_ushort(lo16);
}
__device__ __forceinline__ void split2(float x0, float x1, unsigned& hi, unsigned& lo) {
    __nv_bfloat16 h0 = __float2bfloat16(x0);
    __nv_bfloat16 h1 = __float2bfloat16(x1);
    __nv_bfloat16 l0 = __float2bfloat16(x0 - __bfloat162float(h0));
    __nv_bfloat16 l1 = __float2bfloat16(x1 - __bfloat162float(h1));
    hi = pack_bf2(h0, h1);
    lo = pack_bf2(l0, l1);
}

// =====================================================================
// elementwise fp32 -> bf16 hi/lo split
// =====================================================================
__global__ __launch_bounds__(256) void split_kernel(
    const float4* __restrict__ src, uint2* __restrict__ dh,
    uint2* __restrict__ dl, int n4)
{
    int i = blockIdx.x * blockDim.x + threadIdx.x;
    if (i >= n4) return;
    float4 v = src[i];
    unsigned h0, l0, h1, l1;
    split2(v.x, v.y, h0, l0);
    split2(v.z, v.w, h1, l1);
    dh[i] = make_uint2(h0, h1);
    dl[i] = make_uint2(l0, l1);
}

// =====================================================================
// split-bf16 GEMM v2: pre-split bf16 inputs, fp32 or split bf16 output.
// BM=BN=128, BK=32, 256 threads, warps 2(m) x 4(n).
// =====================================================================
#define A_STRIDE 40
#define B_STRIDE 136

struct GArg {
    const __nv_bfloat16 *Ah, *Al, *Bh, *Bl;
    float* C;
    __nv_bfloat16 *Ch, *Cl;
};

__global__ __launch_bounds__(256) void gemm2(GArg ga0, GArg ga1, int M, int N, int K)
{
    GArg ga = (blockIdx.z == 0) ? ga0 : ga1;

    __shared__ __nv_bfloat16 Ash[128 * A_STRIDE];
    __shared__ __nv_bfloat16 Asl[128 * A_STRIDE];
    __shared__ __nv_bfloat16 Bsh[32 * B_STRIDE];
    __shared__ __nv_bfloat16 Bsl[32 * B_STRIDE];

    const int tid  = threadIdx.x;
    const int warp = tid >> 5;
    const int lane = tid & 31;
    const int wm   = warp >> 2;
    const int wn   = warp & 3;
    const int bm   = blockIdx.y * 128;
    const int bn   = blockIdx.x * 128;

    float acc[4][4][4];
#pragma unroll
    for (int i = 0; i < 4; i++)
#pragma unroll
        for (int j = 0; j < 4; j++)
#pragma unroll
            for (int r = 0; r < 4; r++) acc[i][j][r] = 0.f;

    const unsigned ash = (unsigned)__cvta_generic_to_shared(Ash);
    const unsigned asl = (unsigned)__cvta_generic_to_shared(Asl);
    const unsigned bsh = (unsigned)__cvta_generic_to_shared(Bsh);
    const unsigned bsl = (unsigned)__cvta_generic_to_shared(Bsl);

    // chunk maps: A: 512 chunks (128 rows x 4 x 16B); B: 512 (32 rows x 16)
    const int ac0 = tid, ac1 = tid + 256;
    const int ar0 = ac0 >> 2, au0 = (ac0 & 3) * 8;
    const int ar1 = ac1 >> 2, au1 = (ac1 & 3) * 8;
    const int br0 = ac0 >> 4, bu0 = (ac0 & 15) * 8;
    const int br1 = ac1 >> 4, bu1 = (ac1 & 15) * 8;

    uint4 pah[2], pal[2], pbh[2], pbl[2];
    {
        pah[0] = *(const uint4*)(ga.Ah + (size_t)(bm + ar0) * K + au0);
        pah[1] = *(const uint4*)(ga.Ah + (size_t)(bm + ar1) * K + au1);
        pal[0] = *(const uint4*)(ga.Al + (size_t)(bm + ar0) * K + au0);
        pal[1] = *(const uint4*)(ga.Al + (size_t)(bm + ar1) * K + au1);
        pbh[0] = *(const uint4*)(ga.Bh + (size_t)br0 * N + bn + bu0);
        pbh[1] = *(const uint4*)(ga.Bh + (size_t)br1 * N + bn + bu1);
        pbl[0] = *(const uint4*)(ga.Bl + (size_t)br0 * N + bn + bu0);
        pbl[1] = *(const uint4*)(ga.Bl + (size_t)br1 * N + bn + bu1);
    }

    const int niter = K / 32;
    for (int it = 0; it < niter; it++) {
        *(uint4*)&Ash[ar0 * A_STRIDE + au0] = pah[0];
        *(uint4*)&Ash[ar1 * A_STRIDE + au1] = pah[1];
        *(uint4*)&Asl[ar0 * A_STRIDE + au0] = pal[0];
        *(uint4*)&Asl[ar1 * A_STRIDE + au1] = pal[1];
        *(uint4*)&Bsh[br0 * B_STRIDE + bu0] = pbh[0];
        *(uint4*)&Bsh[br1 * B_STRIDE + bu1] = pbh[1];
        *(uint4*)&Bsl[br0 * B_STRIDE + bu0] = pbl[0];
        *(uint4*)&Bsl[br1 * B_STRIDE + bu1] = pbl[1];
        __syncthreads();

        if (it + 1 < niter) {
            int k0 = (it + 1) * 32;
            pah[0] = *(const uint4*)(ga.Ah + (size_t)(bm + ar0) * K + k0 + au0);
            pah[1] = *(const uint4*)(ga.Ah + (size_t)(bm + ar1) * K + k0 + au1);
            pal[0] = *(const uint4*)(ga.Al + (size_t)(bm + ar0) * K + k0 + au0);
            pal[1] = *(const uint4*)(ga.Al + (size_t)(bm + ar1) * K + k0 + au1);
            pbh[0] = *(const uint4*)(ga.Bh + (size_t)(k0 + br0) * N + bn + bu0);
            pbh[1] = *(const uint4*)(ga.Bh + (size_t)(k0 + br1) * N + bn + bu1);
            pbl[0] = *(const uint4*)(ga.Bl + (size_t)(k0 + br0) * N + bn + bu0);
            pbl[1] = *(const uint4*)(ga.Bl + (size_t)(k0 + br1) * N + bn + bu1);
        }

#pragma unroll
        for (int ks = 0; ks < 32; ks += 16) {
            unsigned ah[4][4], al[4][4];
#pragma unroll
            for (int mi = 0; mi < 4; mi++) {
                unsigned off = 2u * ((unsigned)((wm*64 + mi*16 + (lane & 15)) * A_STRIDE
                                               + ks + (lane >> 4) * 8));
                LDSM_X4(ah[mi][0], ah[mi][1], ah[mi][2], ah[mi][3], ash + off);
                LDSM_X4(al[mi][0], al[mi][1], al[mi][2], al[mi][3], asl + off);
            }
            unsigned bh[4][2], bl[4][2];
#pragma unroll
            for (int nb = 0; nb < 2; nb++) {
                unsigned off = 2u * ((unsigned)((ks + (lane & 15)) * B_STRIDE
                                               + wn*32 + nb*16 + (lane >> 4) * 8));
                unsigned r0, r1, r2, r3;
                LDSM_X4_T(r0, r1, r2, r3, bsh + off);
                bh[2*nb][0] = r0; bh[2*nb][1] = r1;
                bh[2*nb+1][0] = r2; bh[2*nb+1][1] = r3;
                LDSM_X4_T(r0, r1, r2, r3, bsl + off);
                bl[2*nb][0] = r0; bl[2*nb][1] = r1;
                bl[2*nb+1][0] = r2; bl[2*nb+1][1] = r3;
            }
#pragma unroll
            for (int mi = 0; mi < 4; mi++) {
#pragma unroll
                for (int ni = 0; ni < 4; ni++) {
                    MMA16816(acc[mi][ni], ah[mi][0],ah[mi][1],ah[mi][2],ah[mi][3],
                             bh[ni][0], bh[ni][1]);
                    MMA16816(acc[mi][ni], ah[mi][0],ah[mi][1],ah[mi][2],ah[mi][3],
                             bl[ni][0], bl[ni][1]);
                    MMA16816(acc[mi][ni], al[mi][0],al[mi][1],al[mi][2],al[mi][3],
                             bh[ni][0], bh[ni][1]);
                }
            }
        }
        __syncthreads();
    }

    const int g = lane >> 2, q = lane & 3;
#pragma unroll
    for (int mi = 0; mi < 4; mi++) {
#pragma unroll
        for (int ni = 0; ni < 4; ni++) {
            int row = bm + wm*64 + mi*16 + g;
            int col = bn + wn*32 + ni*8 + q*2;
            if (ga.C) {
                *(float2*)&ga.C[(size_t)row * N + col]       = make_float2(acc[mi][ni][0], acc[mi][ni][1]);
                *(float2*)&ga.C[(size_t)(row + 8) * N + col] = make_float2(acc[mi][ni][2], acc[mi][ni][3]);
            }
            if (ga.Ch) {
                unsigned h0, l0;
                split2(acc[mi][ni][0], acc[mi][ni][1], h0, l0);
                *(unsigned*)&ga.Ch[(size_t)row * N + col] = h0;
                *(unsigned*)&ga.Cl[(size_t)row * N + col] = l0;
                split2(acc[mi][ni][2], acc[mi][ni][3], h0, l0);
                *(unsigned*)&ga.Ch[(size_t)(row + 8) * N + col] = h0;
                *(unsigned*)&ga.Cl[(size_t)(row + 8) * N + col] = l0;
            }
        }
    }
}

// =====================================================================
// RoPE v2: reads fp32 q/k proj outputs, rotates, scales q by
// log2(e)/sqrt(HD), writes pre-split bf16 hi/lo for attention.
// =====================================================================
__global__ __launch_bounds__(256) void rope2_kernel(
    const int* __restrict__ pos_w,
    const float* __restrict__ q, const float* __restrict__ k,
    __nv_bfloat16* __restrict__ qh, __nv_bfloat16* __restrict__ ql,
    __nv_bfloat16* __restrict__ kh, __nv_bfloat16* __restrict__ kl)
{
    const int s = blockIdx.x;
    const int tid = threadIdx.x;
    __shared__ float cs[64], sn[64];

    const float QSCALE = (float)(1.4426950408889634 * 0.08838834764831845);

    if (tid < 64) {
        bool is64 = (pos_w[1] == 0);
        int pi = is64 ? pos_w[2 * s] : pos_w[s];
        float p = (float)pi;
        float ex = (float)(2 * tid) / (float)HD;
        float inv = powf(10000.0f, -ex);
        float ang = p * inv;
        sincosf(ang, &sn[tid], &cs[tid]);
    }
    __syncthreads();

    for (int idx = tid; idx < NH * 64; idx += 256) {
        int h = idx >> 6, d = idx & 63;
        size_t base = (size_t)s * QDIM + h * HD;
        float x1 = q[base + d], x2 = q[base + d + 64];
        float c = cs[d], si = sn[d];
        float y1 = (x1 * c - x2 * si) * QSCALE;
        float y2 = (x2 * c + x1 * si) * QSCALE;
        __nv_bfloat16 h1 = __float2bfloat16(y1);
        __nv_bfloat16 h2 = __float2bfloat16(y2);
        qh[base + d]      = h1;
        qh[base + d + 64] = h2;
        ql[base + d]      = __float2bfloat16(y1 - __bfloat162float(h1));
        ql[base + d + 64] = __float2bfloat16(y2 - __bfloat162float(h2));
    }
    for (int idx = tid; idx < NKVH * 64; idx += 256) {
        int h = idx >> 6, d = idx & 63;
        size_t base = (size_t)s * KVDIM + h * HD;
        float x1 = k[base + d], x2 = k[base + d + 64];
        float c = cs[d], si = sn[d];
        float y1 = x1 * c - x2 * si;
        float y2 = x2 * c + x1 * si;
        __nv_bfloat16 h1 = __float2bfloat16(y1);
        __nv_bfloat16 h2 = __float2bfloat16(y2);
        kh[base + d]      = h1;
        kh[base + d + 64] = h2;
        kl[base + d]      = __float2bfloat16(y1 - __bfloat162float(h1));
        kl[base + d + 64] = __float2bfloat16(y2 - __bfloat162float(h2));
    }
}

// =====================================================================
// MMA flash attention v2: pre-split bf16 inputs, cp.async double-buffered
// K/V, split bf16 output. smem: Q 64KB + 2 x 64KB KV buffers = 192KB.
// =====================================================================
#define SMQ_H 0
#define SMQ_L 32768
#define KVBUF0 65536
#define KVSZ   65536
#define OF_KH  0
#define OF_KL  16384
#define OF_VH  32768
#define OF_VL  49152
#define SMEM_ATTN2 196608

__device__ __forceinline__ int swz(int row, int col_b16) {
    return row * 256 + ((((col_b16 >> 3) ^ (row & 7)) << 4)) + ((col_b16 & 7) << 1);
}

__global__ __launch_bounds__(256) void attn_mma2(
    const __nv_bfloat16* __restrict__ Qh, const __nv_bfloat16* __restrict__ Ql,
    const __nv_bfloat16* __restrict__ Kh, const __nv_bfloat16* __restrict__ Kl,
    const __nv_bfloat16* __restrict__ Vh, const __nv_bfloat16* __restrict__ Vl,
    __nv_bfloat16* __restrict__ Oh, __nv_bfloat16* __restrict__ Ol)
{
    extern __shared__ char sm[];
    const unsigned smu = (unsigned)__cvta_generic_to_shared(sm);

    const int tid  = threadIdx.x;
    const int warp = tid >> 5;
    const int lane = tid & 31;
    const int g    = lane >> 2;
    const int qd   = lane & 3;
    const int qb   = blockIdx.x;
    const int h    = blockIdx.y;
    const int kvh  = h >> 2;
    const int i0   = qb * 128;

    const int kb_lo = max(0, qb * 2 - 32);
    const int kb_hi = qb * 2 + 1;

    // ---- prologue: cp.async Q (once) + first KV block ----
    {
        // Q: 128 rows x 16 units, hi+lo
#pragma unroll
        for (int rep = 0; rep < 8; rep++) {
            int chunk = tid + rep * 256;
            int row = chunk >> 4, u = chunk & 15;
            unsigned dsto = row * 256 + (((u ^ (row & 7)) << 4));
            const __nv_bfloat16* sq = Qh + (size_t)(i0 + row) * QDIM + h * HD + u * 8;
            CP_ASYNC16(smu + SMQ_H + dsto, sq);
            const __nv_bfloat16* sl = Ql + (size_t)(i0 + row) * QDIM + h * HD + u * 8;
            CP_ASYNC16(smu + SMQ_L + dsto, sl);
        }
        // KV kb_lo into buffer 0
#pragma unroll
        for (int rep = 0; rep < 4; rep++) {
            int chunk = tid + rep * 256;
            int row = chunk >> 4, u = chunk & 15;
            unsigned dsto = row * 256 + (((u ^ (row & 7)) << 4));
            size_t srco = (size_t)(kb_lo * 64 + row) * KVDIM + kvh * HD + u * 8;
            CP_ASYNC16(smu + KVBUF0 + OF_KH + dsto, Kh + srco);
            CP_ASYNC16(smu + KVBUF0 + OF_KL + dsto, Kl + srco);
            CP_ASYNC16(smu + KVBUF0 + OF_VH + dsto, Vh + srco);
            CP_ASYNC16(smu + KVBUF0 + OF_VL + dsto, Vl + srco);
        }
        CP_COMMIT();
    }

    float o[16][4];
#pragma unroll
    for (int i = 0; i < 16; i++)
#pragma unroll
        for (int c = 0; c < 4; c++) o[i][c] = 0.f;

    float m0 = -1e30f, m1 = -1e30f, l0s = 0.f, l1s = 0.f;

    const int ig0 = i0 + warp * 16 + g;
    const int ig1 = ig0 + 8;

    for (int kb = kb_lo; kb <= kb_hi; kb++) {
        CP_WAIT0();
        __syncthreads();

        const int buf = (kb - kb_lo) & 1;
        const unsigned kvb = smu + KVBUF0 + buf * KVSZ;

        // issue next block into the other buffer
        if (kb + 1 <= kb_hi) {
            const unsigned nb = smu + KVBUF0 + (buf ^ 1) * KVSZ;
#pragma unroll
            for (int rep = 0; rep < 4; rep++) {
                int chunk = tid + rep * 256;
                int row = chunk >> 4, u = chunk & 15;
                unsigned dsto = row * 256 + (((u ^ (row & 7)) << 4));
                size_t srco = (size_t)((kb + 1) * 64 + row) * KVDIM + kvh * HD + u * 8;
                CP_ASYNC16(nb + OF_KH + dsto, Kh + srco);
                CP_ASYNC16(nb + OF_KL + dsto, Kl + srco);
                CP_ASYNC16(nb + OF_VH + dsto, Vh + srco);
                CP_ASYNC16(nb + OF_VL + dsto, Vl + srco);
            }
            CP_COMMIT();
        }

        // ---- S = Q K^T ----
        float S[8][4];
#pragma unroll
        for (int i = 0; i < 8; i++)
#pragma unroll
            for (int c = 0; c < 4; c++) S[i][c] = 0.f;

#pragma unroll
        for (int kc = 0; kc < 8; kc++) {
            unsigned ah0,ah1,ah2,ah3, al0,al1,al2,al3;
            {
                int aoff = swz(warp*16 + (lane & 15), kc*16 + (lane >> 4) * 8);
                LDSM_X4(ah0,ah1,ah2,ah3, smu + SMQ_H + aoff);
                LDSM_X4(al0,al1,al2,al3, smu + SMQ_L + aoff);
            }
#pragma unroll
            for (int ntp = 0; ntp < 4; ntp++) {
                int boff = swz(ntp*16 + (lane & 15), kc*16 + (lane >> 4) * 8);
                unsigned k0,k1,k2,k3, e0,e1,e2,e3;
                LDSM_X4(k0,k1,k2,k3, kvb + OF_KH + boff);
                LDSM_X4(e0,e1,e2,e3, kvb + OF_KL + boff);
                MMA16816(S[2*ntp],   ah0,ah1,ah2,ah3, k0,k2);
                MMA16816(S[2*ntp],   ah0,ah1,ah2,ah3, e0,e2);
                MMA16816(S[2*ntp],   al0,al1,al2,al3, k0,k2);
                MMA16816(S[2*ntp+1], ah0,ah1,ah2,ah3, k1,k3);
                MMA16816(S[2*ntp+1], ah0,ah1,ah2,ah3, e1,e3);
                MMA16816(S[2*ntp+1], al0,al1,al2,al3, k1,k3);
            }
        }

        bool need_mask = (kb >= qb*2) || (kb <= qb*2 - 31);
        if (need_mask) {
#pragma unroll
            for (int nt = 0; nt < 8; nt++) {
                int j0 = kb*64 + nt*8 + 2*qd;
                S[nt][0] = ((unsigned)(ig0 - j0)     <= (unsigned)WIN) ? S[nt][0] : -1e30f;
                S[nt][1] = ((unsigned)(ig0 - j0 - 1) <= (unsigned)WIN) ? S[nt][1] : -1e30f;
                S[nt][2] = ((unsigned)(ig1 - j0)     <= (unsigned)WIN) ? S[nt][2] : -1e30f;
                S[nt][3] = ((unsigned)(ig1 - j0 - 1) <= (unsigned)WIN) ? S[nt][3] : -1e30f;
            }
        }

        float mx0 = -1e30f, mx1 = -1e30f;
#pragma unroll
        for (int nt = 0; nt < 8; nt++) {
            mx0 = fmaxf(mx0, fmaxf(S[nt][0], S[nt][1]));
            mx1 = fmaxf(mx1, fmaxf(S[nt][2], S[nt][3]));
        }
        mx0 = fmaxf(mx0, __shfl_xor_sync(0xffffffffu, mx0, 1));
        mx0 = fmaxf(mx0, __shfl_xor_sync(0xffffffffu, mx0, 2));
        mx1 = fmaxf(mx1, __shfl_xor_sync(0xffffffffu, mx1, 1));
        mx1 = fmaxf(mx1, __shfl_xor_sync(0xffffffffu, mx1, 2));

        float mn0 = fmaxf(m0, mx0);
        float mn1 = fmaxf(m1, mx1);
        float a0 = exp2f(m0 - mn0);
        float a1 = exp2f(m1 - mn1);
        float ok0 = (mn0 > -5e29f) ? 1.f : 0.f;
        float ok1 = (mn1 > -5e29f) ? 1.f : 0.f;
        m0 = mn0; m1 = mn1;
        l0s *= a0; l1s *= a1;

#pragma unroll
        for (int nt = 0; nt < 8; nt++) {
            S[nt][0] = exp2f(S[nt][0] - mn0) * ok0;
            S[nt][1] = exp2f(S[nt][1] - mn0) * ok0;
            S[nt][2] = exp2f(S[nt][2] - mn1) * ok1;
            S[nt][3] = exp2f(S[nt][3] - mn1) * ok1;
            l0s += S[nt][0] + S[nt][1];
            l1s += S[nt][2] + S[nt][3];
        }

#pragma unroll
        for (int i = 0; i < 16; i++) {
            o[i][0] *= a0; o[i][1] *= a0;
            o[i][2] *= a1; o[i][3] *= a1;
        }

        unsigned ph[4][4], pl[4][4];
#pragma unroll
        for (int t = 0; t < 4; t++) {
            split2(S[2*t][0],   S[2*t][1],   ph[t][0], pl[t][0]);
            split2(S[2*t][2],   S[2*t][3],   ph[t][1], pl[t][1]);
            split2(S[2*t+1][0], S[2*t+1][1], ph[t][2], pl[t][2]);
            split2(S[2*t+1][2], S[2*t+1][3], ph[t][3], pl[t][3]);
        }

#pragma unroll
        for (int t = 0; t < 4; t++) {
#pragma unroll
            for (int ntp = 0; ntp < 8; ntp++) {
                int voff = swz(t*16 + (lane & 15), ntp*16 + (lane >> 4) * 8);
                unsigned v0,v1,v2,v3, w0,w1,w2,w3;
                LDSM_X4_T(v0,v1,v2,v3, kvb + OF_VH + voff);
                LDSM_X4_T(w0,w1,w2,w3, kvb + OF_VL + voff);
                MMA16816(o[2*ntp],   ph[t][0],ph[t][1],ph[t][2],ph[t][3], v0,v1);
                MMA16816(o[2*ntp],   ph[t][0],ph[t][1],ph[t][2],ph[t][3], w0,w1);
                MMA16816(o[2*ntp],   pl[t][0],pl[t][1],pl[t][2],pl[t][3], v0,v1);
                MMA16816(o[2*ntp+1], ph[t][0],ph[t][1],ph[t][2],ph[t][3], v2,v3);
                MMA16816(o[2*ntp+1], ph[t][0],ph[t][1],ph[t][2],ph[t][3], w2,w3);
                MMA16816(o[2*ntp+1], pl[t][0],pl[t][1],pl[t][2],pl[t][3], v2,v3);
            }
        }
    }

    l0s += __shfl_xor_sync(0xffffffffu, l0s, 1);
    l0s += __shfl_xor_sync(0xffffffffu, l0s, 2);
    l1s += __shfl_xor_sync(0xffffffffu, l1s, 1);
    l1s += __shfl_xor_sync(0xffffffffu, l1s, 2);
    float inv0 = 1.f / l0s;
    float inv1 = 1.f / l1s;

    // split bf16 epilogue (for o-proj GEMM consumption)
#pragma unroll
    for (int nt = 0; nt < 16; nt++) {
        int col = h * HD + nt * 8 + 2 * qd;
        unsigned h0, l0;
        split2(o[nt][0] * inv0, o[nt][1] * inv0, h0, l0);
        *(unsigned*)&Oh[(size_t)ig0 * QDIM + col] = h0;
        *(unsigned*)&Ol[(size_t)ig0 * QDIM + col] = l0;
        split2(o[nt][2] * inv1, o[nt][3] * inv1, h0, l0);
        *(unsigned*)&Oh[(size_t)ig1 * QDIM + col] = h0;
        *(unsigned*)&Ol[(size_t)ig1 * QDIM + col] = l0;
    }
}

// =====================================================================
extern "C" void kernel_launch(void* const* d_in, const int* in_sizes, int n_in,
                              void* d_out, int out_size)
{
    const float* query = (const float*)d_in[0];
    const float* key   = (const float*)d_in[1];
    const float* value = (const float*)d_in[2];
    const int*   pos   = (const int*)d_in[3];
    const float* wq    = (const float*)d_in[4];
    const float* wk    = (const float*)d_in[5];
    const float* wv    = (const float*)d_in[6];
    const float* wo    = (const float*)d_in[7];
    float*       out   = (float*)d_out;

    float *q_s, *k_s;
    __nv_bfloat16 *qh,*ql,*kh,*kl,*vh,*vl,*ath,*atl;
    __nv_bfloat16 *xqh,*xql,*xkh,*xkl,*xvh,*xvl;
    __nv_bfloat16 *wqh,*wql,*wkh,*wkl,*wvh,*wvl,*woh,*wol;
    cudaGetSymbolAddress((void**)&q_s, g_q);   cudaGetSymbolAddress((void**)&k_s, g_k);
    cudaGetSymbolAddress((void**)&qh, g_qh);   cudaGetSymbolAddress((void**)&ql, g_ql);
    cudaGetSymbolAddress((void**)&kh, g_kh);   cudaGetSymbolAddress((void**)&kl, g_kl);
    cudaGetSymbolAddress((void**)&vh, g_vh);   cudaGetSymbolAddress((void**)&vl, g_vl);
    cudaGetSymbolAddress((void**)&ath, g_ath); cudaGetSymbolAddress((void**)&atl, g_atl);
    cudaGetSymbolAddress((void**)&xqh, g_xqh); cudaGetSymbolAddress((void**)&xql, g_xql);
    cudaGetSymbolAddress((void**)&xkh, g_xkh); cudaGetSymbolAddress((void**)&xkl, g_xkl);
    cudaGetSymbolAddress((void**)&xvh, g_xvh); cudaGetSymbolAddress((void**)&xvl, g_xvl);
    cudaGetSymbolAddress((void**)&wqh, g_wqh); cudaGetSymbolAddress((void**)&wql, g_wql);
    cudaGetSymbolAddress((void**)&wkh, g_wkh); cudaGetSymbolAddress((void**)&wkl, g_wkl);
    cudaGetSymbolAddress((void**)&wvh, g_wvh); cudaGetSymbolAddress((void**)&wvl, g_wvl);
    cudaGetSymbolAddress((void**)&woh, g_woh); cudaGetSymbolAddress((void**)&wol, g_wol);

    cudaFuncSetAttribute(attn_mma2, cudaFuncAttributeMaxDynamicSharedMemorySize, SMEM_ATTN2);

    dim3 blk(256);

    // ---- pre-split inputs and weights ----
    auto launch_split = [&](const float* src, __nv_bfloat16* dh, __nv_bfloat16* dl, size_t n) {
        int n4 = (int)(n / 4);
        split_kernel<<<(n4 + 255) / 256, blk>>>((const float4*)src, (uint2*)dh, (uint2*)dl, n4);
    };
    launch_split(query, xqh, xql, (size_t)SEQ * EMB);
    launch_split(key,   xkh, xkl, (size_t)SEQ * EMB);
    launch_split(value, xvh, xvl, (size_t)SEQ * EMB);
    launch_split(wq, wqh, wql, (size_t)EMB * QDIM);
    launch_split(wk, wkh, wkl, (size_t)EMB * KVDIM);
    launch_split(wv, wvh, wvl, (size_t)EMB * KVDIM);
    launch_split(wo, woh, wol, (size_t)QDIM * EMB);

    // ---- projections ----
    GArg gq  = { xqh, xql, wqh, wql, q_s, nullptr, nullptr };
    gemm2<<<dim3(QDIM/128, SEQ/128, 1), blk>>>(gq, gq, SEQ, QDIM, EMB);

    GArg gk  = { xkh, xkl, wkh, wkl, k_s, nullptr, nullptr };
    GArg gv  = { xvh, xvl, wvh, wvl, nullptr, vh, vl };
    gemm2<<<dim3(KVDIM/128, SEQ/128, 2), blk>>>(gk, gv, SEQ, KVDIM, EMB);

    // ---- rope + split q/k ----
    rope2_kernel<<<SEQ, blk>>>(pos, q_s, k_s, qh, ql, kh, kl);

    // ---- attention ----
    attn_mma2<<<dim3(SEQ/128, NH), blk, SMEM_ATTN2>>>(qh, ql, kh, kl, vh, vl, ath, atl);

    // ---- output projection ----
    GArg go  = { ath, atl, woh, wol, out, nullptr, nullptr };
    gemm2<<<dim3(EMB/128, SEQ/128, 1), blk>>>(go, go, SEQ, EMB, QDIM);
}